// round 1
// baseline (speedup 1.0000x reference)
#include <cuda_runtime.h>
#include <math.h>

#define NUM_CLASSES 200
#define NUM_PROTO   10
#define EMBED_D     512
#define NQ          8192
#define MC_MAX      512
#define EPSILON_    0.01f
#define ITERS       5
#define MOM         0.02f

// Scratch: normalized tokens (16 MB) + label dtype flag
__device__ float g_tok[NQ * EMBED_D];
__device__ int   g_is64;

// ---------------------------------------------------------------------------
// Kernel 0: detect whether labels buffer is int64 (odd 32-bit words all zero)
// or int32. Values are in [0, 200), so int64 high words are exactly 0; an
// int32 buffer of 8192 labels has a nonzero odd-index word with overwhelming
// probability.
// ---------------------------------------------------------------------------
__global__ void detect_kernel(const unsigned* __restrict__ labels_raw) {
    int local = 0;
    for (int i = threadIdx.x; i < NQ / 2; i += blockDim.x) {
        if (labels_raw[2 * i + 1] != 0u) local = 1;
    }
    int any = __syncthreads_or(local);
    if (threadIdx.x == 0) g_is64 = any ? 0 : 1;
}

// ---------------------------------------------------------------------------
// Kernel 1: L2-normalize each token row into g_tok. One block per row,
// 128 threads, float4 loads (512 floats = 128 float4).
// ---------------------------------------------------------------------------
__global__ __launch_bounds__(128) void norm_kernel(const float* __restrict__ tokens) {
    __shared__ float red[4];
    int row = blockIdx.x;
    int tid = threadIdx.x;
    int lane = tid & 31, wid = tid >> 5;

    const float4* src = (const float4*)(tokens + (size_t)row * EMBED_D);
    float4 v = src[tid];
    float ss = v.x * v.x + v.y * v.y + v.z * v.z + v.w * v.w;
    #pragma unroll
    for (int o = 16; o; o >>= 1) ss += __shfl_xor_sync(0xffffffffu, ss, o);
    if (lane == 0) red[wid] = ss;
    __syncthreads();
    float tot = red[0] + red[1] + red[2] + red[3];
    float inv = rsqrtf(tot);
    float4 o4;
    o4.x = v.x * inv; o4.y = v.y * inv; o4.z = v.z * inv; o4.w = v.w * inv;
    ((float4*)(g_tok + (size_t)row * EMBED_D))[tid] = o4;
}

// ---------------------------------------------------------------------------
// Kernel 2: one block per class (200 blocks, 512 threads).
//   Phase 1: order-preserving compaction of token indices with label==c
//   Phase 2: S[p][j] = dot(proto[10c+p], tok_norm[idx[j]])   (S = -C)
//   Phase 3: log-domain Sinkhorn, 5 iterations, in shared memory
//   Phase 4: pi -> column-normalized pi_; new_proto = pi_ @ tok;
//            out = l2norm(0.98*proto + 0.02*new_proto)
// ---------------------------------------------------------------------------
__global__ __launch_bounds__(512) void class_kernel(
    const void* __restrict__ labels_v,
    const float* __restrict__ protos,
    float* __restrict__ out)
{
    __shared__ int   s_idx[MC_MAX];
    __shared__ float S[NUM_PROTO][MC_MAX];
    __shared__ float su[NUM_PROTO];
    __shared__ float sv[MC_MAX];
    __shared__ float red[16];
    __shared__ int   warp_cnt[16];
    __shared__ int   s_m;

    const int c    = blockIdx.x;
    const int tid  = threadIdx.x;
    const int lane = tid & 31;
    const int wid  = tid >> 5;

    const int is64 = g_is64;
    const int* lab32 = (const int*)labels_v;

    // ---- Phase 1: stable compaction of this class's token indices ----
    if (tid == 0) s_m = 0;
    __syncthreads();
    for (int base = 0; base < NQ; base += 512) {
        int i = base + tid;                     // NQ % 512 == 0, always valid
        int lab = is64 ? lab32[2 * i] : lab32[i];
        bool pred = (lab == c);
        unsigned ball = __ballot_sync(0xffffffffu, pred);
        if (lane == 0) warp_cnt[wid] = __popc(ball);
        __syncthreads();
        if (tid == 0) {
            int acc = s_m;
            #pragma unroll
            for (int w = 0; w < 16; w++) { int t = warp_cnt[w]; warp_cnt[w] = acc; acc += t; }
            s_m = acc;
        }
        __syncthreads();
        if (pred) {
            int pos = warp_cnt[wid] + __popc(ball & ((1u << lane) - 1u));
            if (pos < MC_MAX) s_idx[pos] = i;
        }
        __syncthreads();
    }
    const int m = (s_m < MC_MAX) ? s_m : MC_MAX;

    // ---- Phase 2: S[p][j] = proto_row . tok_row (warp per dot product) ----
    {
        int ntask = NUM_PROTO * m;
        for (int t = wid; t < ntask; t += 16) {
            int p = t / (m > 0 ? m : 1);
            int j = t - p * m;
            const float4* pr = (const float4*)(protos + (size_t)(c * NUM_PROTO + p) * EMBED_D);
            const float4* tk = (const float4*)(g_tok + (size_t)s_idx[j] * EMBED_D);
            float dot = 0.f;
            #pragma unroll
            for (int k = 0; k < 4; k++) {
                float4 a = pr[lane + 32 * k];
                float4 b = tk[lane + 32 * k];
                dot += a.x * b.x + a.y * b.y + a.z * b.z + a.w * b.w;
            }
            #pragma unroll
            for (int o = 16; o; o >>= 1) dot += __shfl_xor_sync(0xffffffffu, dot, o);
            if (lane == 0) S[p][j] = dot;   // similarity = -C
        }
    }
    if (tid < NUM_PROTO) su[tid] = 0.f;
    if (tid < MC_MAX)    sv[tid] = 0.f;
    __syncthreads();

    // ---- Phase 3: Sinkhorn (log domain, matches reference recurrence) ----
    if (m > 0) {
        const float log_a = logf(1.0f / (float)NUM_PROTO + 1e-8f);
        const float log_b = logf(1.0f / (float)m + 1e-8f);
        const float inv_eps = 1.0f / EPSILON_;

        for (int it = 0; it < ITERS; it++) {
            // u update: warp p handles row p
            if (wid < NUM_PROTO) {
                int p = wid;
                float up = su[p];
                float mx = -INFINITY;
                for (int j = lane; j < m; j += 32)
                    mx = fmaxf(mx, (S[p][j] + up + sv[j]) * inv_eps);
                #pragma unroll
                for (int o = 16; o; o >>= 1)
                    mx = fmaxf(mx, __shfl_xor_sync(0xffffffffu, mx, o));
                float sum = 0.f;
                for (int j = lane; j < m; j += 32)
                    sum += expf((S[p][j] + up + sv[j]) * inv_eps - mx);
                #pragma unroll
                for (int o = 16; o; o >>= 1)
                    sum += __shfl_xor_sync(0xffffffffu, sum, o);
                if (lane == 0) {
                    float lse = mx + logf(sum);
                    su[p] = EPSILON_ * (log_a - lse) + up;
                }
            }
            __syncthreads();
            // v update: thread j handles column j (uses updated u)
            if (tid < m) {
                int j = tid;
                float vj = sv[j];
                float mx = -INFINITY;
                #pragma unroll
                for (int p = 0; p < NUM_PROTO; p++)
                    mx = fmaxf(mx, (S[p][j] + su[p] + vj) * inv_eps);
                float sum = 0.f;
                #pragma unroll
                for (int p = 0; p < NUM_PROTO; p++)
                    sum += expf((S[p][j] + su[p] + vj) * inv_eps - mx);
                float lse = mx + logf(sum);
                sv[j] = EPSILON_ * (log_b - lse) + vj;
            }
            __syncthreads();
        }

        // pi = exp(kernel(u,v)); column-normalize in place (safe: after the
        // final v update every column's logsumexp == log_b < 0, no overflow)
        if (tid < m) {
            int j = tid;
            float col[NUM_PROTO];
            float cs = 0.f;
            #pragma unroll
            for (int p = 0; p < NUM_PROTO; p++) {
                col[p] = expf((S[p][j] + su[p] + sv[j]) * (1.0f / EPSILON_));
                cs += col[p];
            }
            float inv = 1.0f / cs;
            #pragma unroll
            for (int p = 0; p < NUM_PROTO; p++) S[p][j] = col[p] * inv;
        }
    }
    __syncthreads();

    // ---- Phase 4: new_proto = pi_ @ tok; blend; l2norm; write ----
    // thread tid owns embedding dim d = tid
    float acc[NUM_PROTO];
    #pragma unroll
    for (int p = 0; p < NUM_PROTO; p++) acc[p] = 0.f;
    for (int j = 0; j < m; j++) {
        float t = g_tok[(size_t)s_idx[j] * EMBED_D + tid];
        #pragma unroll
        for (int p = 0; p < NUM_PROTO; p++) acc[p] += S[p][j] * t;
    }

    for (int p = 0; p < NUM_PROTO; p++) {
        int gp = c * NUM_PROTO + p;
        float val = (1.0f - MOM) * protos[(size_t)gp * EMBED_D + tid] + MOM * acc[p];
        float ss = val * val;
        #pragma unroll
        for (int o = 16; o; o >>= 1) ss += __shfl_xor_sync(0xffffffffu, ss, o);
        if (lane == 0) red[wid] = ss;
        __syncthreads();
        if (wid == 0) {
            float r = (lane < 16) ? red[lane] : 0.f;
            #pragma unroll
            for (int o = 8; o; o >>= 1) r += __shfl_xor_sync(0xffffffffu, r, o);
            if (lane == 0) red[0] = r;
        }
        __syncthreads();
        float tot = red[0];
        out[(size_t)gp * EMBED_D + tid] = val * rsqrtf(tot);
        __syncthreads();   // protect red[] before next p
    }
}

// ---------------------------------------------------------------------------
extern "C" void kernel_launch(void* const* d_in, const int* in_sizes, int n_in,
                              void* d_out, int out_size) {
    const float* tokens = (const float*)d_in[0];
    const void*  labels = d_in[1];
    const float* protos = (const float*)d_in[2];
    float* out = (float*)d_out;

    detect_kernel<<<1, 256>>>((const unsigned*)labels);
    norm_kernel<<<NQ, 128>>>(tokens);
    class_kernel<<<NUM_CLASSES, 512>>>(labels, protos, out);
}

// round 2
// speedup vs baseline: 1.4253x; 1.4253x over previous
#include <cuda_runtime.h>
#include <math.h>

#define NUM_CLASSES 200
#define NUM_PROTO   10
#define EMBED_D     512
#define NQ          8192
#define MC_MAX      192     // hard cap on tokens per class (mean 41, sd 6.4)
#define TCAP        40      // token rows cached in smem
#define EPSILON_    0.01f
#define ITERS       5
#define MOM         0.02f
#define NTHREADS    512

// Dynamic smem layout (floats):
//   tok  [TCAP][512]          : TCAP*512
//   proto[10][512]            : 5120
//   S    [10][MC_MAX]         : 10*MC_MAX   (similarity, later pi_)
//   sv   [MC_MAX]
//   invn [MC_MAX]
//   idx  [MC_MAX] (int)
#define OFF_TOK   0
#define OFF_PROTO (OFF_TOK   + TCAP * EMBED_D)
#define OFF_S     (OFF_PROTO + NUM_PROTO * EMBED_D)
#define OFF_SV    (OFF_S     + NUM_PROTO * MC_MAX)
#define OFF_INVN  (OFF_SV    + MC_MAX)
#define OFF_IDX   (OFF_INVN  + MC_MAX)
#define SMEM_FLOATS (OFF_IDX + MC_MAX)
#define SMEM_BYTES  (SMEM_FLOATS * 4)

extern __shared__ float smem_dyn[];

__global__ __launch_bounds__(NTHREADS) void fused_kernel(
    const float* __restrict__ tokens,
    const void*  __restrict__ labels_v,
    const float* __restrict__ protos_g,
    float* __restrict__ out)
{
    __shared__ float su[NUM_PROTO];
    __shared__ float red[16];
    __shared__ int   s_cnt;

    float* tok   = smem_dyn + OFF_TOK;
    float* proto = smem_dyn + OFF_PROTO;
    float* S     = smem_dyn + OFF_S;
    float* sv    = smem_dyn + OFF_SV;
    float* invn  = smem_dyn + OFF_INVN;
    int*   idx   = (int*)(smem_dyn + OFF_IDX);

    const int c    = blockIdx.x;
    const int tid  = threadIdx.x;
    const int lane = tid & 31;
    const int wid  = tid >> 5;
    const int* lab32 = (const int*)labels_v;

    // ---- dtype detection: int64 labels (<200) have all-zero high words ----
    if (tid == 0) s_cnt = 0;
    if (tid < NUM_PROTO) su[tid] = 0.f;
    if (tid < MC_MAX)    sv[tid] = 0.f;
    unsigned hw = ((const unsigned*)labels_v)[2 * tid + 1];
    int any = __syncthreads_or(hw != 0u);   // barrier: also orders s_cnt init
    const int is64 = any ? 0 : 1;

    // ---- compaction of this class's token indices (unordered) ----
    for (int i = tid; i < NQ; i += NTHREADS) {
        int lab = is64 ? lab32[2 * i] : lab32[i];
        if (lab == c) {
            int pos = atomicAdd(&s_cnt, 1);
            if (pos < MC_MAX) idx[pos] = i;
        }
    }

    // ---- load prototypes for this class into smem (float4) ----
    {
        const float4* src = (const float4*)(protos_g + (size_t)c * NUM_PROTO * EMBED_D);
        float4* dst = (float4*)proto;
        #pragma unroll
        for (int i = tid; i < NUM_PROTO * EMBED_D / 4; i += NTHREADS)
            dst[i] = src[i];
    }
    __syncthreads();
    const int m = (s_cnt < MC_MAX) ? s_cnt : MC_MAX;

    // ---- load+normalize token rows; compute S[p][j] = proto_p . tok_j ----
    // warp per row j; lane holds 4 float4 (16 floats) of the raw row
    for (int j = wid; j < m; j += 16) {
        const float4* tk = (const float4*)(tokens + (size_t)idx[j] * EMBED_D);
        float4 r[4];
        float ss = 0.f;
        #pragma unroll
        for (int k = 0; k < 4; k++) {
            r[k] = tk[lane + 32 * k];
            ss += r[k].x * r[k].x + r[k].y * r[k].y + r[k].z * r[k].z + r[k].w * r[k].w;
        }
        #pragma unroll
        for (int o = 16; o; o >>= 1) ss += __shfl_xor_sync(0xffffffffu, ss, o);
        float inv = rsqrtf(ss);
        if (lane == 0) invn[j] = inv;
        if (j < TCAP) {
            float4* dst = (float4*)(tok + (size_t)j * EMBED_D);
            #pragma unroll
            for (int k = 0; k < 4; k++) {
                float4 s4;
                s4.x = r[k].x * inv; s4.y = r[k].y * inv;
                s4.z = r[k].z * inv; s4.w = r[k].w * inv;
                dst[lane + 32 * k] = s4;
            }
        }
        const float4* pr4 = (const float4*)proto;
        #pragma unroll
        for (int p = 0; p < NUM_PROTO; p++) {
            float d = 0.f;
            #pragma unroll
            for (int k = 0; k < 4; k++) {
                float4 a = pr4[p * 128 + lane + 32 * k];
                d += a.x * r[k].x + a.y * r[k].y + a.z * r[k].z + a.w * r[k].w;
            }
            #pragma unroll
            for (int o = 16; o; o >>= 1) d += __shfl_xor_sync(0xffffffffu, d, o);
            if (lane == 0) S[p * MC_MAX + j] = d * inv;   // dot with normalized row
        }
    }
    __syncthreads();

    // ---- Sinkhorn, log domain, 5 iterations (matches reference recurrence) --
    if (m > 0) {
        const float log_a = logf(1.0f / (float)NUM_PROTO + 1e-8f);
        const float log_b = logf(1.0f / (float)m + 1e-8f);
        const float inv_eps = 1.0f / EPSILON_;

        for (int it = 0; it < ITERS; it++) {
            if (wid < NUM_PROTO) {               // u update: warp p = row p
                int p = wid;
                float up = su[p];
                float mx = -INFINITY;
                for (int j = lane; j < m; j += 32)
                    mx = fmaxf(mx, (S[p * MC_MAX + j] + up + sv[j]) * inv_eps);
                #pragma unroll
                for (int o = 16; o; o >>= 1)
                    mx = fmaxf(mx, __shfl_xor_sync(0xffffffffu, mx, o));
                float sum = 0.f;
                for (int j = lane; j < m; j += 32)
                    sum += expf((S[p * MC_MAX + j] + up + sv[j]) * inv_eps - mx);
                #pragma unroll
                for (int o = 16; o; o >>= 1)
                    sum += __shfl_xor_sync(0xffffffffu, sum, o);
                if (lane == 0)
                    su[p] = EPSILON_ * (log_a - (mx + logf(sum))) + up;
            }
            __syncthreads();
            if (tid < m) {                       // v update: thread j = col j
                int j = tid;
                float vj = sv[j];
                float mx = -INFINITY;
                #pragma unroll
                for (int p = 0; p < NUM_PROTO; p++)
                    mx = fmaxf(mx, (S[p * MC_MAX + j] + su[p] + vj) * inv_eps);
                float sum = 0.f;
                #pragma unroll
                for (int p = 0; p < NUM_PROTO; p++)
                    sum += expf((S[p * MC_MAX + j] + su[p] + vj) * inv_eps - mx);
                sv[j] = EPSILON_ * (log_b - (mx + logf(sum))) + vj;
            }
            __syncthreads();
        }

        // pi = exp(kernel); column-normalize in place -> pi_
        // (safe: after final v update each column's logsumexp == log_b < 0)
        if (tid < m) {
            int j = tid;
            float col[NUM_PROTO];
            float cs = 0.f;
            #pragma unroll
            for (int p = 0; p < NUM_PROTO; p++) {
                col[p] = expf((S[p * MC_MAX + j] + su[p] + sv[j]) * (1.0f / EPSILON_));
                cs += col[p];
            }
            float inv = 1.0f / cs;
            #pragma unroll
            for (int p = 0; p < NUM_PROTO; p++) S[p * MC_MAX + j] = col[p] * inv;
        }
    }
    __syncthreads();

    // ---- new_proto = pi_ @ tok; blend; l2norm; write (thread = dim) --------
    float acc[NUM_PROTO];
    #pragma unroll
    for (int p = 0; p < NUM_PROTO; p++) acc[p] = 0.f;
    for (int j = 0; j < m; j++) {
        float t = (j < TCAP) ? tok[(size_t)j * EMBED_D + tid]
                             : tokens[(size_t)idx[j] * EMBED_D + tid] * invn[j];
        #pragma unroll
        for (int p = 0; p < NUM_PROTO; p++) acc[p] += S[p * MC_MAX + j] * t;
    }

    for (int p = 0; p < NUM_PROTO; p++) {
        float val = (1.0f - MOM) * proto[p * EMBED_D + tid] + MOM * acc[p];
        float ss = val * val;
        #pragma unroll
        for (int o = 16; o; o >>= 1) ss += __shfl_xor_sync(0xffffffffu, ss, o);
        if (lane == 0) red[wid] = ss;
        __syncthreads();
        if (wid == 0) {
            float r = (lane < 16) ? red[lane] : 0.f;
            #pragma unroll
            for (int o = 8; o; o >>= 1) r += __shfl_xor_sync(0xffffffffu, r, o);
            if (lane == 0) red[0] = r;
        }
        __syncthreads();
        float tot = red[0];
        out[((size_t)(c * NUM_PROTO + p)) * EMBED_D + tid] = val * rsqrtf(tot);
        __syncthreads();   // protect red[] for next p
    }
}

// ---------------------------------------------------------------------------
extern "C" void kernel_launch(void* const* d_in, const int* in_sizes, int n_in,
                              void* d_out, int out_size) {
    const float* tokens = (const float*)d_in[0];
    const void*  labels = d_in[1];
    const float* protos = (const float*)d_in[2];
    float* out = (float*)d_out;

    cudaFuncSetAttribute(fused_kernel,
                         cudaFuncAttributeMaxDynamicSharedMemorySize, SMEM_BYTES);
    fused_kernel<<<NUM_CLASSES, NTHREADS, SMEM_BYTES>>>(tokens, labels, protos, out);
}

// round 4
// speedup vs baseline: 1.6455x; 1.1545x over previous
#include <cuda_runtime.h>
#include <math.h>

#define NUM_CLASSES 200
#define NUM_PROTO   10
#define EMBED_D     512
#define NQ          8192
#define MC_MAX      192
#define TCAP        40      // token rows staged in smem (mean m=41, sd 6.4)
#define EPSILON_    0.01f
#define ITERS       5
#define MOM         0.02f
#define NT          512

// dynamic smem layout (floats)
#define OFF_TOK   0
#define OFF_PROTO (OFF_TOK   + TCAP * EMBED_D)          // 20480
#define OFF_S     (OFF_PROTO + NUM_PROTO * EMBED_D)     // +5120
#define OFF_SV    (OFF_S     + NUM_PROTO * MC_MAX)      // +1920
#define OFF_INVN  (OFF_SV    + MC_MAX)
#define OFF_IDX   (OFF_INVN  + MC_MAX)
#define SMEM_FLOATS (OFF_IDX + MC_MAX)
#define SMEM_BYTES  (SMEM_FLOATS * 4)                   // 112384 B

__device__ __forceinline__ void cp16(unsigned dst, const void* src) {
    asm volatile("cp.async.cg.shared.global [%0], [%1], 16;\n" :: "r"(dst), "l"(src));
}

extern __shared__ float sm[];

__global__ void __launch_bounds__(NT, 2) fused_kernel(
    const float* __restrict__ tokens,
    const void*  __restrict__ labels_v,
    const float* __restrict__ protos_g,
    float* __restrict__ out)
{
    __shared__ float su[NUM_PROTO];
    __shared__ int   s_cnt;

    float* tok   = sm + OFF_TOK;
    float* proto = sm + OFF_PROTO;
    float* S     = sm + OFF_S;
    float* sv    = sm + OFF_SV;
    float* invn  = sm + OFF_INVN;
    int*   idx   = (int*)(sm + OFF_IDX);

    const int c    = blockIdx.x;
    const int tid  = threadIdx.x;
    const int lane = tid & 31;
    const int wid  = tid >> 5;

    // ---- prefetch prototypes via cp.async (overlaps label latency) ----
    {
        unsigned ps = (unsigned)__cvta_generic_to_shared(proto);
        const char* src = (const char*)(protos_g + (size_t)c * NUM_PROTO * EMBED_D);
        for (int q = tid; q < NUM_PROTO * EMBED_D / 4; q += NT)
            cp16(ps + q * 16, src + q * 16);
        asm volatile("cp.async.commit_group;\n");
    }

    if (tid == 0) s_cnt = 0;
    if (tid < NUM_PROTO) su[tid] = 0.f;
    if (tid < MC_MAX)    sv[tid] = 0.f;

    // ---- dtype detect: int64 labels (<200) have zero high words ----
    unsigned hwd = ((const unsigned*)labels_v)[2 * tid + 1];
    const int is64 = __syncthreads_or(hwd != 0u) ? 0 : 1;  // barrier orders s_cnt

    // ---- label scan: 16 independent loads into registers (max MLP) ----
    int labs[16];
    if (is64) {
        #pragma unroll
        for (int k = 0; k < 16; k++) labs[k] = ((const int2*)labels_v)[tid + NT * k].x;
    } else {
        #pragma unroll
        for (int k = 0; k < 16; k++) labs[k] = ((const int*)labels_v)[tid + NT * k];
    }
    #pragma unroll
    for (int k = 0; k < 16; k++) {
        if (labs[k] == c) {
            int pos = atomicAdd(&s_cnt, 1);
            if (pos < MC_MAX) idx[pos] = tid + NT * k;
        }
    }
    __syncthreads();
    const int m    = (s_cnt < MC_MAX) ? s_cnt : MC_MAX;
    const int mcap = (m < TCAP) ? m : TCAP;

    // ---- bulk-stage raw token rows into smem via cp.async ----
    {
        unsigned ts = (unsigned)__cvta_generic_to_shared(tok);
        for (int t = tid; t < mcap * 128; t += NT) {
            int j = t >> 7, q = t & 127;
            cp16(ts + (unsigned)(j * 128 + q) * 16,
                 (const char*)(tokens + (size_t)idx[j] * EMBED_D) + q * 16);
        }
        asm volatile("cp.async.commit_group;\n");
        asm volatile("cp.async.wait_group 0;\n");
    }
    __syncthreads();

    // ---- normalize rows (in place for staged rows) + S[p][j] dots ----
    for (int j = wid; j < m; j += 16) {
        float4 r[4];
        float ss = 0.f;
        if (j < TCAP) {
            float4* rw = (float4*)(tok + (size_t)j * EMBED_D);
            #pragma unroll
            for (int k = 0; k < 4; k++) {
                r[k] = rw[lane + 32 * k];
                ss += r[k].x*r[k].x + r[k].y*r[k].y + r[k].z*r[k].z + r[k].w*r[k].w;
            }
        } else {
            const float4* tk = (const float4*)(tokens + (size_t)idx[j] * EMBED_D);
            #pragma unroll
            for (int k = 0; k < 4; k++) {
                r[k] = tk[lane + 32 * k];
                ss += r[k].x*r[k].x + r[k].y*r[k].y + r[k].z*r[k].z + r[k].w*r[k].w;
            }
        }
        #pragma unroll
        for (int o = 16; o; o >>= 1) ss += __shfl_xor_sync(0xffffffffu, ss, o);
        float inv = rsqrtf(ss);
        if (lane == 0) invn[j] = inv;
        if (j < TCAP) {                       // write back normalized
            float4* rw = (float4*)(tok + (size_t)j * EMBED_D);
            #pragma unroll
            for (int k = 0; k < 4; k++) {
                float4 s4;
                s4.x = r[k].x*inv; s4.y = r[k].y*inv;
                s4.z = r[k].z*inv; s4.w = r[k].w*inv;
                rw[lane + 32 * k] = s4;
            }
        }
        const float4* pr4 = (const float4*)proto;
        #pragma unroll
        for (int p = 0; p < NUM_PROTO; p++) {
            float d = 0.f;
            #pragma unroll
            for (int k = 0; k < 4; k++) {
                float4 a = pr4[p * 128 + lane + 32 * k];
                d += a.x*r[k].x + a.y*r[k].y + a.z*r[k].z + a.w*r[k].w;
            }
            #pragma unroll
            for (int o = 16; o; o >>= 1) d += __shfl_xor_sync(0xffffffffu, d, o);
            if (lane == 0) S[p * MC_MAX + j] = d * inv;
        }
    }
    __syncthreads();

    // ---- Sinkhorn, log domain, 5 iterations (reference recurrence) ----
    if (m > 0) {
        const float log_a = logf(1.0f / (float)NUM_PROTO + 1e-8f);
        const float log_b = logf(1.0f / (float)m + 1e-8f);
        const float inv_eps = 1.0f / EPSILON_;

        for (int it = 0; it < ITERS; it++) {
            if (wid < NUM_PROTO) {           // u: warp p handles row p
                int p = wid;
                float up = su[p];
                float mx = -INFINITY;
                for (int j = lane; j < m; j += 32)
                    mx = fmaxf(mx, (S[p * MC_MAX + j] + up + sv[j]) * inv_eps);
                #pragma unroll
                for (int o = 16; o; o >>= 1)
                    mx = fmaxf(mx, __shfl_xor_sync(0xffffffffu, mx, o));
                float sum = 0.f;
                for (int j = lane; j < m; j += 32)
                    sum += expf((S[p * MC_MAX + j] + up + sv[j]) * inv_eps - mx);
                #pragma unroll
                for (int o = 16; o; o >>= 1)
                    sum += __shfl_xor_sync(0xffffffffu, sum, o);
                if (lane == 0)
                    su[p] = EPSILON_ * (log_a - (mx + logf(sum))) + up;
            }
            __syncthreads();
            if (tid < m) {                   // v: thread j handles column j
                int j = tid;
                float vj = sv[j];
                float mx = -INFINITY;
                #pragma unroll
                for (int p = 0; p < NUM_PROTO; p++)
                    mx = fmaxf(mx, (S[p * MC_MAX + j] + su[p] + vj) * inv_eps);
                float sum = 0.f;
                #pragma unroll
                for (int p = 0; p < NUM_PROTO; p++)
                    sum += expf((S[p * MC_MAX + j] + su[p] + vj) * inv_eps - mx);
                sv[j] = EPSILON_ * (log_b - (mx + logf(sum))) + vj;
            }
            __syncthreads();
        }

        // pi = exp(kernel); column-normalize in place -> pi_
        if (tid < m) {
            int j = tid;
            float col[NUM_PROTO];
            float cs = 0.f;
            #pragma unroll
            for (int p = 0; p < NUM_PROTO; p++) {
                col[p] = expf((S[p * MC_MAX + j] + su[p] + sv[j]) * (1.0f / EPSILON_));
                cs += col[p];
            }
            float inv = 1.0f / cs;
            #pragma unroll
            for (int p = 0; p < NUM_PROTO; p++) S[p * MC_MAX + j] = col[p] * inv;
        }
    }
    __syncthreads();

    // ---- Phase 4: new_proto = pi_ @ tok, 4 j-groups x 128 float4-dims ----
    const int g  = tid >> 7;        // j-group 0..3
    const int d4 = tid & 127;       // float4 chunk within row
    float4 acc[NUM_PROTO];
    #pragma unroll
    for (int p = 0; p < NUM_PROTO; p++) acc[p] = make_float4(0.f, 0.f, 0.f, 0.f);

    for (int j = g; j < m; j += 4) {
        float4 t4;
        if (j < TCAP) {
            t4 = ((const float4*)tok)[j * 128 + d4];
        } else {
            t4 = ((const float4*)(tokens + (size_t)idx[j] * EMBED_D))[d4];
            float iv = invn[j];
            t4.x *= iv; t4.y *= iv; t4.z *= iv; t4.w *= iv;
        }
        #pragma unroll
        for (int p = 0; p < NUM_PROTO; p++) {
            float w = S[p * MC_MAX + j];
            acc[p].x += w * t4.x; acc[p].y += w * t4.y;
            acc[p].z += w * t4.z; acc[p].w += w * t4.w;
        }
    }
    __syncthreads();                 // all reads of tok done
    float4* stage = (float4*)tok;    // reuse token area: [4][10][128] float4
    #pragma unroll
    for (int p = 0; p < NUM_PROTO; p++)
        stage[(g * NUM_PROTO + p) * 128 + d4] = acc[p];
    __syncthreads();

    // ---- output: warp p reduces groups, blends, l2-normalizes, writes ----
    if (wid < NUM_PROTO) {
        const int p = wid;
        float4 v[4];
        float ss = 0.f;
        #pragma unroll
        for (int q = 0; q < 4; q++) {
            int dd = lane + 32 * q;
            float4 a = stage[(0 * NUM_PROTO + p) * 128 + dd];
            #pragma unroll
            for (int gg = 1; gg < 4; gg++) {
                float4 b = stage[(gg * NUM_PROTO + p) * 128 + dd];
                a.x += b.x; a.y += b.y; a.z += b.z; a.w += b.w;
            }
            float4 pr = ((const float4*)proto)[p * 128 + dd];
            v[q].x = (1.0f - MOM) * pr.x + MOM * a.x;
            v[q].y = (1.0f - MOM) * pr.y + MOM * a.y;
            v[q].z = (1.0f - MOM) * pr.z + MOM * a.z;
            v[q].w = (1.0f - MOM) * pr.w + MOM * a.w;
            ss += v[q].x*v[q].x + v[q].y*v[q].y + v[q].z*v[q].z + v[q].w*v[q].w;
        }
        #pragma unroll
        for (int o = 16; o; o >>= 1) ss += __shfl_xor_sync(0xffffffffu, ss, o);
        float inv = rsqrtf(ss);
        float4* dst = (float4*)(out + ((size_t)(c * NUM_PROTO + p)) * EMBED_D);
        #pragma unroll
        for (int q = 0; q < 4; q++) {
            float4 o4;
            o4.x = v[q].x * inv; o4.y = v[q].y * inv;
            o4.z = v[q].z * inv; o4.w = v[q].w * inv;
            dst[lane + 32 * q] = o4;
        }
    }
}

// ---------------------------------------------------------------------------
extern "C" void kernel_launch(void* const* d_in, const int* in_sizes, int n_in,
                              void* d_out, int out_size) {
    const float* tokens = (const float*)d_in[0];
    const void*  labels = d_in[1];
    const float* protos = (const float*)d_in[2];
    float* out = (float*)d_out;

    cudaFuncSetAttribute(fused_kernel,
                         cudaFuncAttributeMaxDynamicSharedMemorySize, SMEM_BYTES);
    fused_kernel<<<NUM_CLASSES, NT, SMEM_BYTES>>>(tokens, labels, protos, out);
}

// round 6
// speedup vs baseline: 1.6728x; 1.0166x over previous
#include <cuda_runtime.h>
#include <cuda_fp16.h>
#include <math.h>

#define NUM_CLASSES 200
#define NUM_PROTO   10
#define EMBED_D     512
#define NQ          8192
#define MC_MAX      192
#define TCAP        64      // token rows staged (half precision); max m ~60
#define EPSILON_    0.01f
#define ITERS       5
#define MOM         0.02f
#define NT          512

// dynamic smem layout (bytes)
//   tok_h : TCAP*512 halves            = 65536   (later reused as fp32 stage)
//   proto : 10*512 fp32                = 20480
//   S     : 10*MC_MAX fp32             = 7680
//   sv    : MC_MAX fp32                = 768
//   invn  : MC_MAX fp32                = 768
//   idx   : MC_MAX int                 = 768
#define OFFB_TOKH  0
#define OFFB_PROTO 65536
#define OFFB_S     (OFFB_PROTO + 20480)
#define OFFB_SV    (OFFB_S + NUM_PROTO * MC_MAX * 4)
#define OFFB_INVN  (OFFB_SV + MC_MAX * 4)
#define OFFB_IDX   (OFFB_INVN + MC_MAX * 4)
#define SMEM_BYTES (OFFB_IDX + MC_MAX * 4)              // 96000

__device__ __forceinline__ void cp16(unsigned dst, const void* src) {
    asm volatile("cp.async.cg.shared.global [%0], [%1], 16;\n" :: "r"(dst), "l"(src));
}

extern __shared__ char smc[];

__global__ void __launch_bounds__(NT, 2) fused_kernel(
    const float* __restrict__ tokens,
    const void*  __restrict__ labels_v,
    const float* __restrict__ protos_g,
    float* __restrict__ out)
{
    __shared__ float su[NUM_PROTO];
    __shared__ int   s_cnt;

    __half2* tok_h = (__half2*)(smc + OFFB_TOKH);   // [TCAP][256]
    float*   proto = (float*)(smc + OFFB_PROTO);
    float*   S     = (float*)(smc + OFFB_S);
    float*   sv    = (float*)(smc + OFFB_SV);
    float*   invn  = (float*)(smc + OFFB_INVN);
    int*     idx   = (int*)(smc + OFFB_IDX);

    const int c    = blockIdx.x;
    const int tid  = threadIdx.x;
    const int lane = tid & 31;
    const int wid  = tid >> 5;

    // ---- prefetch prototypes via cp.async (overlaps label latency) ----
    {
        unsigned ps = (unsigned)__cvta_generic_to_shared(proto);
        const char* src = (const char*)(protos_g + (size_t)c * NUM_PROTO * EMBED_D);
        for (int q = tid; q < NUM_PROTO * EMBED_D / 4; q += NT)
            cp16(ps + q * 16, src + q * 16);
        asm volatile("cp.async.commit_group;\n");
    }

    if (tid == 0) s_cnt = 0;
    if (tid < NUM_PROTO) su[tid] = 0.f;
    if (tid < MC_MAX)    sv[tid] = 0.f;

    // ---- dtype detect: int64 labels (<200) have zero high words ----
    unsigned hwd = ((const unsigned*)labels_v)[2 * tid + 1];
    const int is64 = __syncthreads_or(hwd != 0u) ? 0 : 1;  // barrier orders s_cnt

    // ---- label scan: wide int4 loads, all in flight at once ----
    if (is64) {
        int4 v[8];
        const int4* L = (const int4*)labels_v;          // 2 labels per int4
        #pragma unroll
        for (int k = 0; k < 8; k++) v[k] = L[tid + NT * k];
        #pragma unroll
        for (int k = 0; k < 8; k++) {
            int base = 2 * (tid + NT * k);
            if (v[k].x == c) { int p = atomicAdd(&s_cnt, 1); if (p < MC_MAX) idx[p] = base; }
            if (v[k].z == c) { int p = atomicAdd(&s_cnt, 1); if (p < MC_MAX) idx[p] = base + 1; }
        }
    } else {
        int4 v[4];
        const int4* L = (const int4*)labels_v;          // 4 labels per int4
        #pragma unroll
        for (int k = 0; k < 4; k++) v[k] = L[tid + NT * k];
        #pragma unroll
        for (int k = 0; k < 4; k++) {
            int base = 4 * (tid + NT * k);
            if (v[k].x == c) { int p = atomicAdd(&s_cnt, 1); if (p < MC_MAX) idx[p] = base; }
            if (v[k].y == c) { int p = atomicAdd(&s_cnt, 1); if (p < MC_MAX) idx[p] = base + 1; }
            if (v[k].z == c) { int p = atomicAdd(&s_cnt, 1); if (p < MC_MAX) idx[p] = base + 2; }
            if (v[k].w == c) { int p = atomicAdd(&s_cnt, 1); if (p < MC_MAX) idx[p] = base + 3; }
        }
    }
    asm volatile("cp.async.wait_group 0;\n");   // protos resident
    __syncthreads();
    const int m = (s_cnt < MC_MAX) ? s_cnt : MC_MAX;

    // ---- Phase 2: warp per row: load fp32, normalize, store half2, 10 dots --
    for (int j = wid; j < m; j += 16) {
        const float4* tk = (const float4*)(tokens + (size_t)idx[j] * EMBED_D);
        float4 r[4];
        float ss = 0.f;
        #pragma unroll
        for (int k = 0; k < 4; k++) {
            r[k] = tk[lane + 32 * k];
            ss += r[k].x*r[k].x + r[k].y*r[k].y + r[k].z*r[k].z + r[k].w*r[k].w;
        }
        #pragma unroll
        for (int o = 16; o; o >>= 1) ss += __shfl_xor_sync(0xffffffffu, ss, o);
        float inv = rsqrtf(ss);
        if (lane == 0) invn[j] = inv;
        if (j < TCAP) {
            __half2* row = tok_h + (size_t)j * 256;
            #pragma unroll
            for (int k = 0; k < 4; k++) {
                int h2 = (lane + 32 * k) * 2;
                row[h2]     = __floats2half2_rn(r[k].x * inv, r[k].y * inv);
                row[h2 + 1] = __floats2half2_rn(r[k].z * inv, r[k].w * inv);
            }
        }
        const float4* pr4 = (const float4*)proto;
        #pragma unroll
        for (int p = 0; p < NUM_PROTO; p++) {
            float d = 0.f;
            #pragma unroll
            for (int k = 0; k < 4; k++) {
                float4 a = pr4[p * 128 + lane + 32 * k];
                d += a.x*r[k].x + a.y*r[k].y + a.z*r[k].z + a.w*r[k].w;
            }
            #pragma unroll
            for (int o = 16; o; o >>= 1) d += __shfl_xor_sync(0xffffffffu, d, o);
            if (lane == 0) S[p * MC_MAX + j] = d * inv;
        }
    }
    __syncthreads();

    // ---- Phase 3: Sinkhorn, log domain (reference recurrence) ----
    if (m > 0) {
        const float log_a = logf(1.0f / (float)NUM_PROTO + 1e-8f);
        const float log_b = logf(1.0f / (float)m + 1e-8f);
        const float inv_eps = 1.0f / EPSILON_;

        for (int it = 0; it < ITERS; it++) {
            if (wid < NUM_PROTO) {           // u: warp p
                int p = wid;
                float up = su[p];
                float mx = -INFINITY;
                for (int j = lane; j < m; j += 32)
                    mx = fmaxf(mx, (S[p * MC_MAX + j] + up + sv[j]) * inv_eps);
                #pragma unroll
                for (int o = 16; o; o >>= 1)
                    mx = fmaxf(mx, __shfl_xor_sync(0xffffffffu, mx, o));
                float sum = 0.f;
                for (int j = lane; j < m; j += 32)
                    sum += expf((S[p * MC_MAX + j] + up + sv[j]) * inv_eps - mx);
                #pragma unroll
                for (int o = 16; o; o >>= 1)
                    sum += __shfl_xor_sync(0xffffffffu, sum, o);
                if (lane == 0)
                    su[p] = EPSILON_ * (log_a - (mx + logf(sum))) + up;
            }
            __syncthreads();
            if (tid < m) {                   // v: thread j
                int j = tid;
                float vj = sv[j];
                float mx = -INFINITY;
                #pragma unroll
                for (int p = 0; p < NUM_PROTO; p++)
                    mx = fmaxf(mx, (S[p * MC_MAX + j] + su[p] + vj) * inv_eps);
                float sum = 0.f;
                #pragma unroll
                for (int p = 0; p < NUM_PROTO; p++)
                    sum += expf((S[p * MC_MAX + j] + su[p] + vj) * inv_eps - mx);
                sv[j] = EPSILON_ * (log_b - (mx + logf(sum))) + vj;
            }
            __syncthreads();
        }

        // pi = exp(kernel); column-normalize -> pi_ (safe: col lse == log_b < 0)
        if (tid < m) {
            int j = tid;
            float col[NUM_PROTO];
            float cs = 0.f;
            #pragma unroll
            for (int p = 0; p < NUM_PROTO; p++) {
                col[p] = expf((S[p * MC_MAX + j] + su[p] + sv[j]) * (1.0f / EPSILON_));
                cs += col[p];
            }
            float inv = 1.0f / cs;
            #pragma unroll
            for (int p = 0; p < NUM_PROTO; p++) S[p * MC_MAX + j] = col[p] * inv;
        }
    }
    __syncthreads();

    // ---- Phase 4: new_proto = pi_ @ tok; 2 j-groups x 256 float2-lanes ----
    const int g  = tid >> 8;        // j-group 0..1
    const int d2 = tid & 255;       // float2 chunk within row
    float2 acc[NUM_PROTO];
    #pragma unroll
    for (int p = 0; p < NUM_PROTO; p++) acc[p] = make_float2(0.f, 0.f);

    for (int j = g; j < m; j += 2) {
        float2 t2;
        if (j < TCAP) {
            t2 = __half22float2(tok_h[(size_t)j * 256 + d2]);
        } else {                    // safety fallback (m > 64: effectively never)
            const float2* tr = (const float2*)(tokens + (size_t)idx[j] * EMBED_D);
            t2 = tr[d2];
            float iv = invn[j];
            t2.x *= iv; t2.y *= iv;
        }
        #pragma unroll
        for (int p = 0; p < NUM_PROTO; p++) {
            float w = S[p * MC_MAX + j];
            acc[p].x += w * t2.x;
            acc[p].y += w * t2.y;
        }
    }
    __syncthreads();                 // all reads of tok_h done
    float2* stage = (float2*)(smc + OFFB_TOKH);   // [2][10][256] float2 = 40960 B
    #pragma unroll
    for (int p = 0; p < NUM_PROTO; p++)
        stage[(g * NUM_PROTO + p) * 256 + d2] = acc[p];
    __syncthreads();

    // ---- epilogue: warp p reduces groups, blends, l2-normalizes, writes ----
    if (wid < NUM_PROTO) {
        const int p = wid;
        float2 v[8];
        float ss = 0.f;
        const float2* pr2 = (const float2*)proto;
        #pragma unroll
        for (int q = 0; q < 8; q++) {
            int dd = lane + 32 * q;
            float2 a = stage[(0 * NUM_PROTO + p) * 256 + dd];
            float2 b = stage[(1 * NUM_PROTO + p) * 256 + dd];
            float2 pr = pr2[p * 256 + dd];
            v[q].x = (1.0f - MOM) * pr.x + MOM * (a.x + b.x);
            v[q].y = (1.0f - MOM) * pr.y + MOM * (a.y + b.y);
            ss += v[q].x * v[q].x + v[q].y * v[q].y;
        }
        #pragma unroll
        for (int o = 16; o; o >>= 1) ss += __shfl_xor_sync(0xffffffffu, ss, o);
        float inv = rsqrtf(ss);
        float2* dst = (float2*)(out + ((size_t)(c * NUM_PROTO + p)) * EMBED_D);
        #pragma unroll
        for (int q = 0; q < 8; q++) {
            float2 o2;
            o2.x = v[q].x * inv;
            o2.y = v[q].y * inv;
            dst[lane + 32 * q] = o2;
        }
    }
}

// ---------------------------------------------------------------------------
extern "C" void kernel_launch(void* const* d_in, const int* in_sizes, int n_in,
                              void* d_out, int out_size) {
    const float* tokens = (const float*)d_in[0];
    const void*  labels = d_in[1];
    const float* protos = (const float*)d_in[2];
    float* out = (float*)d_out;

    cudaFuncSetAttribute(fused_kernel,
                         cudaFuncAttributeMaxDynamicSharedMemorySize, SMEM_BYTES);
    fused_kernel<<<NUM_CLASSES, NT, SMEM_BYTES>>>(tokens, labels, protos, out);
}

// round 7
// speedup vs baseline: 1.7603x; 1.0523x over previous
#include <cuda_runtime.h>
#include <cuda_fp16.h>
#include <math.h>

#define NUM_CLASSES 200
#define NUM_PROTO   10
#define EMBED_D     512
#define NQ          8192
#define MC_MAX      192
#define TCAP        64
#define EPSILON_    0.01f
#define ITERS       5
#define MOM         0.02f
#define NT          512

// dynamic smem layout (bytes)
#define OFFB_TOKH  0                                     // TCAP*512 halves = 65536
#define OFFB_PROTO 65536                                 // 10*512 fp32 = 20480
#define OFFB_S     (OFFB_PROTO + 20480)                  // 10*MC_MAX fp32
#define OFFB_SV    (OFFB_S + NUM_PROTO * MC_MAX * 4)
#define OFFB_INVN  (OFFB_SV + MC_MAX * 4)
#define OFFB_IDX   (OFFB_INVN + MC_MAX * 4)
#define SMEM_BYTES (OFFB_IDX + MC_MAX * 4)               // 96000

__device__ __forceinline__ void cp16(unsigned dst, const void* src) {
    asm volatile("cp.async.cg.shared.global [%0], [%1], 16;\n" :: "r"(dst), "l"(src));
}

extern __shared__ char smc[];

__global__ void __launch_bounds__(NT, 2) fused_kernel(
    const float* __restrict__ tokens,
    const void*  __restrict__ labels_v,
    const float* __restrict__ protos_g,
    float* __restrict__ out)
{
    __shared__ float su[NUM_PROTO];
    __shared__ int   s_cnt;

    __half2* tok_h = (__half2*)(smc + OFFB_TOKH);   // [TCAP][256]
    float*   proto = (float*)(smc + OFFB_PROTO);
    float*   S     = (float*)(smc + OFFB_S);
    float*   sv    = (float*)(smc + OFFB_SV);
    float*   invn  = (float*)(smc + OFFB_INVN);
    int*     idx   = (int*)(smc + OFFB_IDX);

    const int c    = blockIdx.x;
    const int tid  = threadIdx.x;
    const int lane = tid & 31;
    const int wid  = tid >> 5;

    // ---- prefetch prototypes via cp.async (overlaps label latency) ----
    {
        unsigned ps = (unsigned)__cvta_generic_to_shared(proto);
        const char* src = (const char*)(protos_g + (size_t)c * NUM_PROTO * EMBED_D);
        for (int q = tid; q < NUM_PROTO * EMBED_D / 4; q += NT)
            cp16(ps + q * 16, src + q * 16);
        asm volatile("cp.async.commit_group;\n");
    }

    if (tid == 0) s_cnt = 0;
    if (tid < NUM_PROTO) su[tid] = 0.f;
    if (tid < MC_MAX)    sv[tid] = 0.f;

    // ---- dtype detect: int64 labels (<200) have zero high words ----
    unsigned hwd = ((const unsigned*)labels_v)[2 * tid + 1];
    const int is64 = __syncthreads_or(hwd != 0u) ? 0 : 1;  // barrier orders s_cnt

    // ---- label scan: wide int4 loads, all in flight at once ----
    if (is64) {
        int4 v[8];
        const int4* L = (const int4*)labels_v;          // 2 labels per int4
        #pragma unroll
        for (int k = 0; k < 8; k++) v[k] = L[tid + NT * k];
        #pragma unroll
        for (int k = 0; k < 8; k++) {
            int base = 2 * (tid + NT * k);
            if (v[k].x == c) { int p = atomicAdd(&s_cnt, 1); if (p < MC_MAX) idx[p] = base; }
            if (v[k].z == c) { int p = atomicAdd(&s_cnt, 1); if (p < MC_MAX) idx[p] = base + 1; }
        }
    } else {
        int4 v[4];
        const int4* L = (const int4*)labels_v;          // 4 labels per int4
        #pragma unroll
        for (int k = 0; k < 4; k++) v[k] = L[tid + NT * k];
        #pragma unroll
        for (int k = 0; k < 4; k++) {
            int base = 4 * (tid + NT * k);
            if (v[k].x == c) { int p = atomicAdd(&s_cnt, 1); if (p < MC_MAX) idx[p] = base; }
            if (v[k].y == c) { int p = atomicAdd(&s_cnt, 1); if (p < MC_MAX) idx[p] = base + 1; }
            if (v[k].z == c) { int p = atomicAdd(&s_cnt, 1); if (p < MC_MAX) idx[p] = base + 2; }
            if (v[k].w == c) { int p = atomicAdd(&s_cnt, 1); if (p < MC_MAX) idx[p] = base + 3; }
        }
    }
    asm volatile("cp.async.wait_group 0;\n");   // protos resident
    __syncthreads();
    const int m = (s_cnt < MC_MAX) ? s_cnt : MC_MAX;

    // ---- Pre-pass: warp per row: norm -> invn, stage fp16 (warms L1) ----
    for (int j = wid; j < m; j += 16) {
        const float4* tk = (const float4*)(tokens + (size_t)idx[j] * EMBED_D);
        float4 r[4];
        float ss = 0.f;
        #pragma unroll
        for (int k = 0; k < 4; k++) {
            r[k] = tk[lane + 32 * k];
            ss += r[k].x*r[k].x + r[k].y*r[k].y + r[k].z*r[k].z + r[k].w*r[k].w;
        }
        #pragma unroll
        for (int o = 16; o; o >>= 1) ss += __shfl_xor_sync(0xffffffffu, ss, o);
        float inv = rsqrtf(ss);
        if (lane == 0) invn[j] = inv;
        if (j < TCAP) {
            __half2* row = tok_h + (size_t)j * 256;
            #pragma unroll
            for (int k = 0; k < 4; k++) {
                int h2 = (lane + 32 * k) * 2;
                row[h2]     = __floats2half2_rn(r[k].x * inv, r[k].y * inv);
                row[h2 + 1] = __floats2half2_rn(r[k].z * inv, r[k].w * inv);
            }
        }
    }
    __syncthreads();

    // ---- Phase 2: 5 proto-pairs x 3 row-subsets; protos in registers ----
    // warp w<15: pair q=w/3 owns protos {2q,2q+1}; rows j = w%3, step 3
    if (wid < 15) {
        const int q  = wid / 3;
        const int rs = wid - 3 * q;
        float4 pa[4], pb[4];
        {
            const float4* pr4 = (const float4*)proto;
            #pragma unroll
            for (int k = 0; k < 4; k++) {
                pa[k] = pr4[(2 * q)     * 128 + lane + 32 * k];
                pb[k] = pr4[(2 * q + 1) * 128 + lane + 32 * k];
            }
        }
        for (int j = rs; j < m; j += 3) {
            const float4* tk = (const float4*)(tokens + (size_t)idx[j] * EMBED_D);
            float d0 = 0.f, d1 = 0.f;
            #pragma unroll
            for (int k = 0; k < 4; k++) {
                float4 t = tk[lane + 32 * k];          // L1-hot after pre-pass
                d0 += pa[k].x*t.x + pa[k].y*t.y + pa[k].z*t.z + pa[k].w*t.w;
                d1 += pb[k].x*t.x + pb[k].y*t.y + pb[k].z*t.z + pb[k].w*t.w;
            }
            #pragma unroll
            for (int o = 16; o; o >>= 1) {
                d0 += __shfl_xor_sync(0xffffffffu, d0, o);
                d1 += __shfl_xor_sync(0xffffffffu, d1, o);
            }
            if (lane == 0) {
                float iv = invn[j];
                S[(2 * q)     * MC_MAX + j] = d0 * iv;
                S[(2 * q + 1) * MC_MAX + j] = d1 * iv;
            }
        }
    }
    __syncthreads();

    // ---- Phase 3: Sinkhorn, log domain (reference recurrence) ----
    if (m > 0) {
        const float log_a = logf(1.0f / (float)NUM_PROTO + 1e-8f);
        const float log_b = logf(1.0f / (float)m + 1e-8f);
        const float inv_eps = 1.0f / EPSILON_;

        for (int it = 0; it < ITERS; it++) {
            if (wid < NUM_PROTO) {           // u: warp p
                int p = wid;
                float up = su[p];
                float mx = -INFINITY;
                for (int j = lane; j < m; j += 32)
                    mx = fmaxf(mx, (S[p * MC_MAX + j] + up + sv[j]) * inv_eps);
                #pragma unroll
                for (int o = 16; o; o >>= 1)
                    mx = fmaxf(mx, __shfl_xor_sync(0xffffffffu, mx, o));
                float sum = 0.f;
                for (int j = lane; j < m; j += 32)
                    sum += expf((S[p * MC_MAX + j] + up + sv[j]) * inv_eps - mx);
                #pragma unroll
                for (int o = 16; o; o >>= 1)
                    sum += __shfl_xor_sync(0xffffffffu, sum, o);
                if (lane == 0)
                    su[p] = EPSILON_ * (log_a - (mx + logf(sum))) + up;
            }
            __syncthreads();
            if (tid < m) {                   // v: thread j
                int j = tid;
                float vj = sv[j];
                float mx = -INFINITY;
                #pragma unroll
                for (int p = 0; p < NUM_PROTO; p++)
                    mx = fmaxf(mx, (S[p * MC_MAX + j] + su[p] + vj) * inv_eps);
                float sum = 0.f;
                #pragma unroll
                for (int p = 0; p < NUM_PROTO; p++)
                    sum += expf((S[p * MC_MAX + j] + su[p] + vj) * inv_eps - mx);
                sv[j] = EPSILON_ * (log_b - (mx + logf(sum))) + vj;
            }
            __syncthreads();
        }

        // pi = exp(kernel); column-normalize -> pi_ (safe: col lse == log_b < 0)
        if (tid < m) {
            int j = tid;
            float col[NUM_PROTO];
            float cs = 0.f;
            #pragma unroll
            for (int p = 0; p < NUM_PROTO; p++) {
                col[p] = expf((S[p * MC_MAX + j] + su[p] + sv[j]) * (1.0f / EPSILON_));
                cs += col[p];
            }
            float inv = 1.0f / cs;
            #pragma unroll
            for (int p = 0; p < NUM_PROTO; p++) S[p * MC_MAX + j] = col[p] * inv;
        }
    }
    __syncthreads();

    // ---- Phase 4: new_proto = pi_ @ tok; 2 j-groups x 256 float2-lanes ----
    const int g  = tid >> 8;
    const int d2 = tid & 255;
    float2 acc[NUM_PROTO];
    #pragma unroll
    for (int p = 0; p < NUM_PROTO; p++) acc[p] = make_float2(0.f, 0.f);

    for (int j = g; j < m; j += 2) {
        float2 t2;
        if (j < TCAP) {
            t2 = __half22float2(tok_h[(size_t)j * 256 + d2]);
        } else {                    // safety fallback (m > 64: effectively never)
            const float2* tr = (const float2*)(tokens + (size_t)idx[j] * EMBED_D);
            t2 = tr[d2];
            float iv = invn[j];
            t2.x *= iv; t2.y *= iv;
        }
        #pragma unroll
        for (int p = 0; p < NUM_PROTO; p++) {
            float w = S[p * MC_MAX + j];
            acc[p].x += w * t2.x;
            acc[p].y += w * t2.y;
        }
    }
    __syncthreads();                 // all reads of tok_h done
    float2* stage = (float2*)(smc + OFFB_TOKH);   // [2][10][256] float2
    #pragma unroll
    for (int p = 0; p < NUM_PROTO; p++)
        stage[(g * NUM_PROTO + p) * 256 + d2] = acc[p];
    __syncthreads();

    // ---- epilogue: warp p reduces groups, blends, l2-normalizes, writes ----
    if (wid < NUM_PROTO) {
        const int p = wid;
        float2 v[8];
        float ss = 0.f;
        const float2* pr2 = (const float2*)proto;
        #pragma unroll
        for (int q = 0; q < 8; q++) {
            int dd = lane + 32 * q;
            float2 a = stage[(0 * NUM_PROTO + p) * 256 + dd];
            float2 b = stage[(1 * NUM_PROTO + p) * 256 + dd];
            float2 pr = pr2[p * 256 + dd];
            v[q].x = (1.0f - MOM) * pr.x + MOM * (a.x + b.x);
            v[q].y = (1.0f - MOM) * pr.y + MOM * (a.y + b.y);
            ss += v[q].x * v[q].x + v[q].y * v[q].y;
        }
        #pragma unroll
        for (int o = 16; o; o >>= 1) ss += __shfl_xor_sync(0xffffffffu, ss, o);
        float inv = rsqrtf(ss);
        float2* dst = (float2*)(out + ((size_t)(c * NUM_PROTO + p)) * EMBED_D);
        #pragma unroll
        for (int q = 0; q < 8; q++) {
            float2 o2;
            o2.x = v[q].x * inv;
            o2.y = v[q].y * inv;
            dst[lane + 32 * q] = o2;
        }
    }
}

// ---------------------------------------------------------------------------
extern "C" void kernel_launch(void* const* d_in, const int* in_sizes, int n_in,
                              void* d_out, int out_size) {
    const float* tokens = (const float*)d_in[0];
    const void*  labels = d_in[1];
    const float* protos = (const float*)d_in[2];
    float* out = (float*)d_out;

    cudaFuncSetAttribute(fused_kernel,
                         cudaFuncAttributeMaxDynamicSharedMemorySize, SMEM_BYTES);
    fused_kernel<<<NUM_CLASSES, NT, SMEM_BYTES>>>(tokens, labels, protos, out);
}